// round 17
// baseline (speedup 1.0000x reference)
#include <cuda_runtime.h>
#include <cuda_fp16.h>

#define SVOL  4096000        // 160^3
#define NTOT  8192000        // 2 * 160^3
#define NQ    2048000        // NTOT / 4

// ---- p skeleton smem layout (halves), tile 32x32, zchunk 16, 2 z-slices per iter ----
#define OFF_STAGE 0          // 2 x [36][48]   (stride 1728)
#define OFF_ROWMN 3456       // 2 x [36][40]   (stride 1440)
#define OFF_M2D   6336       // ring4 [34][40] (stride 1360)
#define OFF_ERO   11776      // ring3 [34][40] (stride 1360)
#define OFF_E2D   15856      // ring4 [32][32] (stride 1024)
#define SM_HALVES 19952
#define SM_BYTES  (SM_HALVES * 2)   // 39904

// ---- y bit skeleton smem layout (words) — 6-phase separable ----
#define W5    5
#define WSL   800
#define WBAT  128000
#define YW    256000
#define YOFF_X   0           // [800]
#define YOFF_WT  800         // [800] transient (w-erode / w-dilate)
#define YOFF_WH  1600        // ring3 [800]
#define YOFF_E   4000        // ring2 [800]
#define YOFF_D   5600        // ring3 [800]

#define HPINF __ushort_as_half((unsigned short)0x7C00)
#define HNINF __ushort_as_half((unsigned short)0xFC00)

struct __align__(8) h4 { __half2 a, b; };

__device__ double g_acc[14];         // zero-initialized at load; k_fin re-zeroes after use
__device__ __half g_Xp[NTOT];
__device__ __half g_Xp2[NTOT];
__device__ __half g_Porig[NTOT];
__device__ unsigned int g_Yb0[YW];
__device__ unsigned int g_Yb[YW];
__device__ unsigned int g_Yb2[YW];

__device__ __forceinline__ h4 h4fill(__half v) {
    h4 o; o.a = __half2half2(v); o.b = o.a; return o;
}
__device__ __forceinline__ h4 h4min3(h4 x, h4 y, h4 z) {
    h4 o;
    o.a = __hmin2(x.a, __hmin2(y.a, z.a));
    o.b = __hmin2(x.b, __hmin2(y.b, z.b));
    return o;
}
__device__ __forceinline__ h4 h4max3(h4 x, h4 y, h4 z) {
    h4 o;
    o.a = __hmax2(x.a, __hmax2(y.a, z.a));
    o.b = __hmax2(x.b, __hmax2(y.b, z.b));
    return o;
}
__device__ __forceinline__ h4 shiftMin(__half l, h4 c, __half r) {
    __half2 sl  = __halves2half2(l, __low2half(c.a));
    __half2 sr  = __halves2half2(__high2half(c.a), __low2half(c.b));
    __half2 sr2 = __halves2half2(__high2half(c.b), r);
    h4 o;
    o.a = __hmin2(__hmin2(sl, c.a), sr);
    o.b = __hmin2(__hmin2(sr, c.b), sr2);
    return o;
}
__device__ __forceinline__ h4 shiftMax(__half l, h4 c, __half r) {
    __half2 sl  = __halves2half2(l, __low2half(c.a));
    __half2 sr  = __halves2half2(__high2half(c.a), __low2half(c.b));
    __half2 sr2 = __halves2half2(__high2half(c.b), r);
    h4 o;
    o.a = __hmax2(__hmax2(sl, c.a), sr);
    o.b = __hmax2(__hmax2(sr, c.b), sr2);
    return o;
}
// 2D-max of 3 consecutive ero rows (40-pitch), column base 4+g*4
__device__ __forceinline__ h4 max2d(const __half* ep) {
    h4 ra = shiftMax(ep[-1], *(const h4*)ep, ep[4]);
    h4 rb = shiftMax(ep[39], *(const h4*)(ep + 40), ep[44]);
    h4 rc = shiftMax(ep[79], *(const h4*)(ep + 80), ep[84]);
    return h4max3(ra, rb, rc);
}

template <int NV>
__device__ __forceinline__ void blockAddTo(const float* vals, double* gout) {
    __shared__ float red[NV][8];
    int tid = threadIdx.x, lane = tid & 31, w = tid >> 5;
#pragma unroll
    for (int k = 0; k < NV; k++) {
        float v = vals[k];
#pragma unroll
        for (int o = 16; o; o >>= 1) v += __shfl_down_sync(0xffffffffu, v, o);
        if (lane == 0) red[k][w] = v;
    }
    __syncthreads();
    if (w == 0) {
#pragma unroll
        for (int k = 0; k < NV; k++) {
            float v = (lane < 8) ? red[k][lane] : 0.0f;
#pragma unroll
            for (int o = 4; o; o >>= 1) v += __shfl_down_sync(0xffffffffu, v, o);
            if (lane == 0) atomicAdd(&gout[k], (double)v);
        }
    }
}

// Fused: log-softmax, CE, dice accumulators, Porig (fp16), y bit-pack.
// 4 quads (16 voxels) per thread; 2000 blocks x 256.
__global__ void __launch_bounds__(256) k_init(const float* __restrict__ logits,
                                              const int* __restrict__ target) {
    __shared__ unsigned char nib[1024];
    int tid = threadIdx.x;
    int q0 = blockIdx.x * 1024 + tid;

    float ce = 0.f, i0 = 0.f, i1 = 0.f, i2 = 0.f;
    float s0 = 0.f, s1 = 0.f, s2 = 0.f, c0 = 0.f, c1 = 0.f, c2 = 0.f;

#pragma unroll
    for (int u = 0; u < 4; u++) {
        int q = q0 + u * 256;
        int e = q * 4;
        int b = (e >= SVOL) ? 1 : 0;
        int s = e - b * SVOL;
        const float* lp = logits + (size_t)b * 3 * SVOL + s;
        float4 L0 = *(const float4*)(lp);
        float4 L1 = *(const float4*)(lp + SVOL);
        float4 L2 = *(const float4*)(lp + 2 * SVOL);
        int4 ti = ((const int4*)target)[q];
        int tg[4] = {ti.x, ti.y, ti.z, ti.w};
        float a0[4] = {L0.x, L0.y, L0.z, L0.w};
        float a1[4] = {L1.x, L1.y, L1.z, L1.w};
        float a2[4] = {L2.x, L2.y, L2.z, L2.w};

        float pv[4];
        unsigned nb = 0;
#pragma unroll
        for (int j = 0; j < 4; j++) {
            float x0 = a0[j], x1 = a1[j], x2 = a2[j];
            float m = fmaxf(x0, fmaxf(x1, x2));
            float e0 = __expf(x0 - m), e1 = __expf(x1 - m), e2 = __expf(x2 - m);
            float sum = e0 + e1 + e2;
            float inv = __fdividef(1.0f, sum);
            float p0 = e0 * inv, p1 = e1 * inv, p2 = e2 * inv;
            float ls = __logf(sum);
            int t = tg[j];
            float lt = (t == 0) ? x0 : ((t == 1) ? x1 : x2);
            ce += (m + ls - lt);
            s0 += p0; s1 += p1; s2 += p2;
            if (t == 0)      { i0 += p0; c0 += 1.f; }
            else if (t == 1) { i1 += p1; c1 += 1.f; }
            else             { i2 += p2; c2 += 1.f; }
            pv[j] = fminf(fmaxf(1.0f - p0, 0.0f), 1.0f);
            if (t != 0) nb |= (1u << j);
        }
        h4 PV;
        PV.a = __floats2half2_rn(pv[0], pv[1]);
        PV.b = __floats2half2_rn(pv[2], pv[3]);
        ((h4*)g_Porig)[q] = PV;      // iteration 0 reads Porig directly
        nib[u * 256 + tid] = (unsigned char)nb;
    }
    __syncthreads();
    // nib[idx] holds quad blockIdx*1024 + idx, so word wi = blockIdx*128 + tid
    // packs quads wi*8 .. wi*8+7.
    if (tid < 128) {
        unsigned w = 0;
#pragma unroll
        for (int k = 0; k < 8; k++)
            w |= ((unsigned)nib[tid * 8 + k]) << (4 * k);
        int wi = blockIdx.x * 128 + tid;
        g_Yb0[wi] = w;
        g_Yb[wi] = w;
    }

    float vals[10] = {ce, i0, i1, i2, s0, s1, s2, c0, c1, c2};
    blockAddTo<10>(vals, g_acc);
}

// ---------------- merged skeleton iteration -----------------
// blocks [0,80): bit y skeleton (chunk 4, 6-phase separable).
// blocks [80,580): fp16 p skeleton (tile 32x32, zchunk 16, 2 slices/iter,
//                  A/B/C phases + fused D+E+F epilogue => 3 barriers per 2 slices).
// On it==7, blocks also accumulate the clDice sums.

__device__ __forceinline__ void p_skel_block(__half* sm, int bi, int it) {
    __half* stage = sm + OFF_STAGE;
    __half* rowmn = sm + OFF_ROWMN;
    __half* m2d   = sm + OFF_M2D;
    __half* ero   = sm + OFF_ERO;
    __half* e2d   = sm + OFF_E2D;

    const __half* src = (it == 0) ? g_Porig : ((it & 1) ? g_Xp2 : g_Xp);
    __half*       dst = (it & 1) ? g_Xp : g_Xp2;
    bool last = (it == 7);

    int tid = threadIdx.x;
    int r = bi;
    int b = r / 250; r %= 250;
    int zc = r / 25; int t = r % 25;
    int h0 = (t / 5) * 32, w0 = (t % 5) * 32;
    int z0 = zc * 16;
    int base = b * SVOL;

    float accS = 0.f, accSY = 0.f;

    // one-time pad fill (both stage buffers, cols 0..5 and 42..47 stay +inf)
    for (int i = tid; i < 864; i += 256) {
        int s = i / 432, j = i % 432;
        int row = j / 12, c = j % 12;
        stage[s * 1728 + row * 48 + ((c < 6) ? c : c + 36)] = HPINF;
    }

    for (int zb = z0 - 2; zb <= z0 + 16; zb += 2) {
        // ---- A: stage x slices zb, zb+1 ----
        for (int i = tid; i < 576; i += 256) {
            int s = i / 288, j = i % 288;
            int row = j >> 3, qw = j & 7;
            int zl = zb + s;
            int h = h0 + row - 2;
            h4 v = h4fill(HPINF);
            if ((unsigned)zl < 160u && (unsigned)h < 160u)
                v = *(const h4*)(src + base + (zl * 160 + h) * 160 + w0 + qw * 4);
            *(h4*)&stage[s * 1728 + row * 48 + 8 + qw * 4] = v;
        }
        for (int i = tid; i < 288; i += 256) {            // halos w in {-2,-1,32,33}
            int s = i / 144, j = i % 144;
            int row = j >> 2, k = j & 3;
            int w = (k < 2) ? (k - 2) : (k + 30);
            int zl = zb + s;
            int h = h0 + row - 2, ww = w0 + w;
            __half v = HPINF;
            if ((unsigned)zl < 160u && (unsigned)h < 160u && (unsigned)ww < 160u)
                v = src[base + (zl * 160 + h) * 160 + ww];
            stage[s * 1728 + row * 48 + 8 + w] = v;
        }
        __syncthreads();
        // ---- B: row-min along w (both slices) ----
        for (int i = tid; i < 720; i += 256) {
            int s = i / 360, j = i % 360;
            int g = j % 10, row = j / 10;
            const __half* sp = &stage[s * 1728 + row * 48 + 4 + g * 4];
            h4 o = shiftMin(sp[-1], *(const h4*)sp, sp[4]);
            *(h4*)&rowmn[s * 1440 + row * 40 + g * 4] = o;
        }
        __syncthreads();
        // ---- C: col-min -> m2d[zb], m2d[zb+1]; z-min -> ero[zb-1], ero[zb] ----
        int mA = (zb + 6) & 3, mB = (zb + 7) & 3;       // slots zb-2, zb-1
        int m0 = (zb + 8) & 3, m1 = (zb + 9) & 3;       // slots zb,   zb+1
        int e0s = (zb + 8) % 3, e1s = (zb + 9) % 3;     // ero slots zb-1, zb
        bool zv0 = ((unsigned)(zb - 1) < 160u);
        bool zv1 = ((unsigned)zb < 160u);
        for (int i = tid; i < 340; i += 256) {
            int g = i % 10, mrow = i / 10;
            int off = mrow * 40 + g * 4;
            h4 v0, v1;
            {
                h4 r0 = *(h4*)&rowmn[off];
                h4 r1 = *(h4*)&rowmn[off + 40];
                h4 r2 = *(h4*)&rowmn[off + 80];
                v0 = h4min3(r0, r1, r2);
            }
            {
                h4 r0 = *(h4*)&rowmn[1440 + off];
                h4 r1 = *(h4*)&rowmn[1440 + off + 40];
                h4 r2 = *(h4*)&rowmn[1440 + off + 80];
                v1 = h4min3(r0, r1, r2);
            }
            *(h4*)&m2d[m0 * 1360 + off] = v0;
            *(h4*)&m2d[m1 * 1360 + off] = v1;
            h4 ma = *(h4*)&m2d[mA * 1360 + off];
            h4 mb = *(h4*)&m2d[mB * 1360 + off];
            h4 eA = zv0 ? h4min3(ma, mb, v0) : h4fill(HNINF);
            h4 eB = zv1 ? h4min3(mb, v0, v1) : h4fill(HNINF);
            *(h4*)&ero[e0s * 1360 + off] = eA;
            *(h4*)&ero[e1s * 1360 + off] = eB;
        }
        __syncthreads();
        // ---- D+E+F fused: 2D-max of ero -> e2d[zb-1], e2d[zb]; outputs zb-2, zb-1 ----
        {
            int g = tid & 7, h = tid >> 3;     // exactly 256 items
            int off = h * 32 + g * 4;
            h4 v0 = max2d(&ero[e0s * 1360 + h * 40 + 4 + g * 4]);   // e2d[zb-1]
            h4 v1 = max2d(&ero[e1s * 1360 + h * 40 + 4 + g * 4]);   // e2d[zb]
            *(h4*)&e2d[((zb + 7) & 3) * 1024 + off] = v0;
            *(h4*)&e2d[((zb + 8) & 3) * 1024 + off] = v1;

            int za = zb - 2;
            if (za >= z0) {
                __half2 z2 = __float2half2_rn(0.0f);
                // output za = zb-2: e2d slices za-1, za, za+1=v0
                {
                    h4 ea = *(h4*)&e2d[((zb + 5) & 3) * 1024 + off];   // e2d[zb-3]
                    h4 eb = *(h4*)&e2d[((zb + 6) & 3) * 1024 + off];   // e2d[zb-2]
                    h4 op = h4max3(ea, eb, v0);
                    h4 er = *(h4*)&ero[((zb + 7) % 3) * 1360 + (h + 1) * 40 + 4 + g * 4];
                    int vox = base + (za * 160 + h0 + h) * 160 + w0 + g * 4;
                    h4 xv = *(const h4*)(src + vox);
                    h4 o;
                    o.a = __hmax2(__hsub2(xv.a, __hmax2(__hsub2(op.a, er.a), z2)), z2);
                    o.b = __hmax2(__hsub2(xv.b, __hmax2(__hsub2(op.b, er.b), z2)), z2);
                    *(h4*)(dst + vox) = o;
                    if (last) {
                        float2 f01 = __half22float2(o.a), f23 = __half22float2(o.b);
                        int q = vox >> 2;
                        unsigned nb4 = (g_Yb0[q >> 3] >> ((q & 7) * 4)) & 0xFu;
                        accS += f01.x + f01.y + f23.x + f23.y;
                        accSY += (nb4 & 1 ? f01.x : 0.f) + (nb4 & 2 ? f01.y : 0.f)
                               + (nb4 & 4 ? f23.x : 0.f) + (nb4 & 8 ? f23.y : 0.f);
                    }
                }
                // output zB = zb-1: e2d slices zb-2, zb-1=v0, zb=v1
                {
                    int zB = zb - 1;
                    h4 eb = *(h4*)&e2d[((zb + 6) & 3) * 1024 + off];
                    h4 op = h4max3(eb, v0, v1);
                    h4 er = *(h4*)&ero[e0s * 1360 + (h + 1) * 40 + 4 + g * 4];
                    int vox = base + (zB * 160 + h0 + h) * 160 + w0 + g * 4;
                    h4 xv = *(const h4*)(src + vox);
                    h4 o;
                    o.a = __hmax2(__hsub2(xv.a, __hmax2(__hsub2(op.a, er.a), z2)), z2);
                    o.b = __hmax2(__hsub2(xv.b, __hmax2(__hsub2(op.b, er.b), z2)), z2);
                    *(h4*)(dst + vox) = o;
                    if (last) {
                        float2 f01 = __half22float2(o.a), f23 = __half22float2(o.b);
                        int q = vox >> 2;
                        unsigned nb4 = (g_Yb0[q >> 3] >> ((q & 7) * 4)) & 0xFu;
                        accS += f01.x + f01.y + f23.x + f23.y;
                        accSY += (nb4 & 1 ? f01.x : 0.f) + (nb4 & 2 ? f01.y : 0.f)
                               + (nb4 & 4 ? f23.x : 0.f) + (nb4 & 8 ? f23.y : 0.f);
                    }
                }
            }
        }
        // no trailing sync:
        //   next A writes stage (last read in B, 2 barriers before next A's writes);
        //   next C rewrites the ero slots read here only after 2 more barriers (A, B).
    }

    if (last) {
        float vals[2] = {accS, accSY};
        blockAddTo<2>(vals, g_acc + 10);
    }
}

// Bit-domain y skeleton, 4 output slices per block, 6-phase separable.
__device__ __forceinline__ void y_skel_block(unsigned int* su, int bi2, int it) {
    unsigned int* X  = su + YOFF_X;
    unsigned int* WT = su + YOFF_WT;
    unsigned int* WH = su + YOFF_WH;   // ring3
    unsigned int* E  = su + YOFF_E;    // ring2
    unsigned int* D  = su + YOFF_D;    // ring3

    int flip = it & 1;
    const unsigned int* src = flip ? g_Yb2 : g_Yb;
    unsigned int*       dst = flip ? g_Yb  : g_Yb2;
    bool last = (it == 7);

    int tid = threadIdx.x;
    int b = bi2 / 40, c = bi2 % 40;
    int z0 = c * 4, z1 = z0 + 3;
    int gbase = b * WBAT;

    float accY = 0.f, accYP = 0.f;

    for (int zl = z0 - 2; zl <= z1 + 2; ++zl) {
        {
            bool zok = ((unsigned)zl < 160u);
            for (int i = tid; i < 800; i += 256)
                X[i] = zok ? src[gbase + zl * 800 + i] : 0xFFFFFFFFu;
        }
        __syncthreads();
        for (int i = tid; i < 800; i += 256) {
            int j = i % W5;
            unsigned w = X[i];
            unsigned l = j > 0 ? X[i - 1] : 0xFFFFFFFFu;
            unsigned r = j < 4 ? X[i + 1] : 0xFFFFFFFFu;
            WT[i] = w & ((w << 1) | (l >> 31)) & ((w >> 1) | (r << 31));
        }
        __syncthreads();
        {
            int ws = (zl + 6) % 3;
            for (int i = tid; i < 800; i += 256) {
                int r = i / W5;
                unsigned w = WT[i];
                unsigned up = r > 0   ? WT[i - W5] : 0xFFFFFFFFu;
                unsigned dn = r < 159 ? WT[i + W5] : 0xFFFFFFFFu;
                WH[ws * 800 + i] = w & up & dn;
            }
        }
        __syncthreads();
        int ze = zl - 1;
        int es = (ze + 2) & 1;
        {
            bool zev = ((unsigned)ze < 160u);
            int wa = (ze + 5) % 3, wb = (ze + 6) % 3, wc = (ze + 7) % 3;
            for (int i = tid; i < 800; i += 256) {
                unsigned e = WH[wa * 800 + i] & WH[wb * 800 + i] & WH[wc * 800 + i];
                E[es * 800 + i] = zev ? e : 0u;
            }
        }
        __syncthreads();
        for (int i = tid; i < 800; i += 256) {
            int j = i % W5;
            unsigned w = E[es * 800 + i];
            unsigned l = j > 0 ? E[es * 800 + i - 1] : 0u;
            unsigned r = j < 4 ? E[es * 800 + i + 1] : 0u;
            WT[i] = w | (w << 1) | (l >> 31) | (w >> 1) | (r << 31);
        }
        __syncthreads();
        {
            int ds = (ze + 6) % 3;
            for (int i = tid; i < 800; i += 256) {
                int r = i / W5;
                unsigned w = WT[i];
                unsigned up = r > 0   ? WT[i - W5] : 0u;
                unsigned dn = r < 159 ? WT[i + W5] : 0u;
                D[ds * 800 + i] = w | up | dn;
            }
        }
        __syncthreads();
        int z = zl - 2;
        if (z >= z0) {
            int da = (z + 5) % 3, db = (z + 6) % 3, dc = (z + 7) % 3;
            int ez = (z + 2) & 1;
            for (int i = tid; i < 800; i += 256) {
                unsigned open = D[da * 800 + i] | D[db * 800 + i] | D[dc * 800 + i];
                unsigned x = src[gbase + z * 800 + i];
                int wi = gbase + z * 800 + i;
                unsigned dw = x & (~open | E[ez * 800 + i]);
                dst[wi] = dw;
                if (last && dw) {
                    accY += (float)__popc(dw);
#pragma unroll
                    for (int nb = 0; nb < 8; nb++) {
                        unsigned nb4 = (dw >> (nb * 4)) & 0xFu;
                        if (nb4) {
                            h4 p = ((const h4*)g_Porig)[wi * 8 + nb];
                            float2 pa = __half22float2(p.a), pb = __half22float2(p.b);
                            accYP += (nb4 & 1 ? pa.x : 0.f) + (nb4 & 2 ? pa.y : 0.f)
                                   + (nb4 & 4 ? pb.x : 0.f) + (nb4 & 8 ? pb.y : 0.f);
                        }
                    }
                }
            }
        }
    }

    if (last) {
        float vals[2] = {accY, accYP};
        blockAddTo<2>(vals, g_acc + 12);
    }
}

__global__ void __launch_bounds__(256, 4) k_skel(int it) {
    extern __shared__ __half smh[];
    int bi = blockIdx.x;
    if (bi < 80) y_skel_block((unsigned int*)smh, bi, it);
    else         p_skel_block(smh, bi - 80, it);
}

__global__ void k_fin(float* out) {
    double ce = g_acc[0] / (double)NTOT;
    double dsum = 0.0;
#pragma unroll
    for (int c = 0; c < 3; c++) {
        double I = g_acc[1 + c], P = g_acc[4 + c], T = g_acc[7 + c];
        dsum += (2.0 * I + 1e-5) / (P + T + 1e-5);
    }
    double base = ce + (1.0 - dsum / 3.0);
    double tprec = g_acc[11] / (g_acc[10] + 1e-6);
    double tsens = g_acc[13] / (g_acc[12] + 1e-6);
    double cl = 2.0 * tprec * tsens / (tprec + tsens + 1e-6);
    out[0] = (float)(base + 0.5 * (1.0 - cl));
    // re-zero accumulators for the next (graph-replayed) invocation
#pragma unroll
    for (int i = 0; i < 14; i++) g_acc[i] = 0.0;
}

extern "C" void kernel_launch(void* const* d_in, const int* in_sizes, int n_in,
                              void* d_out, int out_size) {
    const float* logits = (const float*)d_in[0];
    const int* target = (const int*)d_in[1];

    cudaFuncSetAttribute((const void*)k_skel,
                         cudaFuncAttributeMaxDynamicSharedMemorySize, SM_BYTES);

    k_init<<<NQ / 1024, 256>>>(logits, target);
    for (int it = 0; it < 8; ++it)
        k_skel<<<580, 256, SM_BYTES>>>(it);
    k_fin<<<1, 1>>>((float*)d_out);
}